// round 12
// baseline (speedup 1.0000x reference)
#include <cuda_runtime.h>
#include <cuda_fp16.h>
#include <cstdint>

#define M_DIM 16384
#define N_DIM 8192
#define K_DIM 64

#define THREADS 128            // 4 warps
#define M_CTA 128              // warp covers 32 m
#define NSPLIT 4
#define NRANGE (N_DIM / NSPLIT)      // 2048
#define NSTEPS (NRANGE / 16)         // 128 per CTA

// fp16 B fragments: u32 idx = ((s*4 + ktp)*32 + lane)*4 + j
#define BFRAG_U32 (512 * 4 * 32 * 4)    // 1MB
#define NPAIRS (N_DIM / 2)

typedef unsigned long long ull;

// ---- device scratch ----
__device__ uint32_t g_Bfrag[BFRAG_U32];
// per n-pair: {bx0,bx1, by0,by1, bz0,bz1, c0,c1}; b=-2e^2 x, c=e^2|x|^2+1
__device__ float g_Xpk[NPAIRS * 8];
__device__ float g_part[NSPLIT][M_DIM * K_DIM];  // partials, 16MB

// ---- helpers ----
__device__ __forceinline__ ull ffma2(ull a, ull b, ull c) {
    ull d; asm("fma.rn.f32x2 %0, %1, %2, %3;" : "=l"(d) : "l"(a), "l"(b), "l"(c)); return d;
}
__device__ __forceinline__ ull fadd2(ull a, ull b) {
    ull d; asm("add.rn.f32x2 %0, %1, %2;" : "=l"(d) : "l"(a), "l"(b)); return d;
}
__device__ __forceinline__ ull splat2(float v) {
    ull d; asm("mov.b64 %0, {%1, %1};" : "=l"(d) : "f"(v)); return d;
}
__device__ __forceinline__ void unpack2(ull p, float& lo, float& hi) {
    asm("mov.b64 {%0, %1}, %2;" : "=f"(lo), "=f"(hi) : "l"(p));
}
__device__ __forceinline__ float fast_sqrt(float x) {
    float r; asm("sqrt.approx.f32 %0, %1;" : "=f"(r) : "f"(x)); return r;
}
// NOTE: non-volatile — pure register op; lets ptxas interleave scalar work
// between HMMAs instead of honoring textual order.
__device__ __forceinline__ void mma_fp16(float* d, uint32_t a0, uint32_t a1,
                                         uint32_t a2, uint32_t a3,
                                         uint32_t b0, uint32_t b1) {
    asm("mma.sync.aligned.m16n8k16.row.col.f32.f16.f16.f32 "
        "{%0,%1,%2,%3}, {%4,%5,%6,%7}, {%8,%9}, {%0,%1,%2,%3};"
        : "+f"(d[0]), "+f"(d[1]), "+f"(d[2]), "+f"(d[3])
        : "r"(a0), "r"(a1), "r"(a2), "r"(a3), "r"(b0), "r"(b1));
}

// ---- merged prep: X pair vectors + W fp16 fragment shredding ----
__global__ __launch_bounds__(256)
void prep_all(const float* __restrict__ W, const float* __restrict__ X,
              const float* __restrict__ epsp) {
    int idx = blockIdx.x * 256 + threadIdx.x;

    if (idx < NPAIRS) {   // adjacent pair p -> n = 2p, 2p+1
        float e = *epsp;
        float e2 = e * e;
        const float* x0 = X + (size_t)(2 * idx) * 3;
        float a0 = x0[0], a1 = x0[1], a2 = x0[2];
        float b0 = x0[3], b1 = x0[4], b2 = x0[5];
        float* o = g_Xpk + (size_t)idx * 8;
        o[0] = -2.0f * e2 * a0; o[1] = -2.0f * e2 * b0;
        o[2] = -2.0f * e2 * a1; o[3] = -2.0f * e2 * b1;
        o[4] = -2.0f * e2 * a2; o[5] = -2.0f * e2 * b2;
        o[6] = fmaf(e2, a0 * a0 + a1 * a1 + a2 * a2, 1.0f);
        o[7] = fmaf(e2, b0 * b0 + b1 * b1 + b2 * b2, 1.0f);
    }

    // B fragment shred (idx covers BFRAG_U32)
    {
        int j   = idx & 3;
        int t   = (idx >> 2) & 31;
        int ktp = (idx >> 7) & 3;
        int s   = idx >> 9;

        int kt = ktp * 2 + (j >> 1);
        int km = (t & 3) * 2 + (j & 1) * 8;   // contraction n within step
        int nm = t >> 2;                      // output k within tile
        int kout = kt * 8 + nm;
        int n = s * 16 + km;

        float w0 = W[(size_t)kout * N_DIM + n];
        float w1 = W[(size_t)kout * N_DIM + n + 1];
        uint32_t packed;
        asm("cvt.rn.f16x2.f32 %0, %1, %2;" : "=r"(packed) : "f"(w1), "f"(w0));
        g_Bfrag[idx] = packed;
    }
}

// ---- main kernel ----
__global__ __launch_bounds__(THREADS, 4)
void rbf_fp16(const float* __restrict__ Xp, const float* __restrict__ epsp) {
    const int tid  = threadIdx.x;
    const int warp = tid >> 5;
    const int lane = tid & 31;
    const int ns   = blockIdx.y;
    const int mwb  = blockIdx.x * M_CTA + warp * 32;   // warp m-base
    const int s0   = ns * NSTEPS;                      // first n-step

    const float e = *epsp;
    const float e2 = e * e;

    // raw Xp coords + Pm = e^2 |xp|^2 for this thread's 4 rows: ci = mtile*2 + u
    ull xs[4], ys[4], zs[4], pm[4];
#pragma unroll
    for (int i = 0; i < 4; i++) {
        int mtile = i >> 1, u = i & 1;
        int m = mwb + mtile * 16 + u * 8 + (lane >> 2);
        float px = Xp[m * 3 + 0], py = Xp[m * 3 + 1], pz = Xp[m * 3 + 2];
        xs[i] = splat2(px);
        ys[i] = splat2(py);
        zs[i] = splat2(pz);
        pm[i] = splat2(e2 * (px * px + py * py + pz * pz));
    }

    float acc[2][8][4];
#pragma unroll
    for (int t = 0; t < 2; t++)
#pragma unroll
        for (int k = 0; k < 8; k++)
#pragma unroll
            for (int j = 0; j < 4; j++) acc[t][k][j] = 0.0f;

    const float* xp = g_Xpk + ((size_t)s0 * 8 + (lane & 3)) * 8;
    const uint4* bf = reinterpret_cast<const uint4*>(g_Bfrag) + (size_t)s0 * 4 * 32 + lane;

#pragma unroll 2
    for (int s = 0; s < NSTEPS; s++) {
        // B fragments for this step (4 x LDG.128)
        uint4 bfr0 = __ldg(bf + 0 * 32);
        uint4 bfr1 = __ldg(bf + 1 * 32);
        uint4 bfr2 = __ldg(bf + 2 * 32);
        uint4 bfr3 = __ldg(bf + 3 * 32);
        bf += 4 * 32;

        // pair vectors: p=0 at +0, p=1 at +32 floats; (bx,by) then (bz,c)
        ulonglong2 A0 = *reinterpret_cast<const ulonglong2*>(xp);
        ulonglong2 B0 = *reinterpret_cast<const ulonglong2*>(xp + 4);
        ulonglong2 A1 = *reinterpret_cast<const ulonglong2*>(xp + 32);
        ulonglong2 B1 = *reinterpret_cast<const ulonglong2*>(xp + 36);
        xp += 64;

        // ---- mtile 0: phi -> fragments, MMAs; mtile 1 phi sits between ----
        uint32_t ah0[4], ah1[4];
#pragma unroll
        for (int u = 0; u < 2; u++) {
            int ci = u;  // mtile 0
#pragma unroll
            for (int p = 0; p < 2; p++) {
                ull base = fadd2(p ? B1.y : B0.y, pm[ci]);
                ull tt = ffma2(xs[ci], p ? A1.x : A0.x,
                         ffma2(ys[ci], p ? A1.y : A0.y,
                         ffma2(zs[ci], p ? B1.x : B0.x, base)));
                float t0, t1; unpack2(tt, t0, t1);
                float sq0 = fast_sqrt(t0), sq1 = fast_sqrt(t1);
                uint32_t hb;
                asm("cvt.rn.f16x2.f32 %0, %1, %2;" : "=r"(hb) : "f"(sq1), "f"(sq0));
                ah0[u + 2 * p] = hb;
            }
        }
        mma_fp16(acc[0][0], ah0[0], ah0[1], ah0[2], ah0[3], bfr0.x, bfr0.y);
        mma_fp16(acc[0][1], ah0[0], ah0[1], ah0[2], ah0[3], bfr0.z, bfr0.w);
        mma_fp16(acc[0][2], ah0[0], ah0[1], ah0[2], ah0[3], bfr1.x, bfr1.y);
        mma_fp16(acc[0][3], ah0[0], ah0[1], ah0[2], ah0[3], bfr1.z, bfr1.w);
        mma_fp16(acc[0][4], ah0[0], ah0[1], ah0[2], ah0[3], bfr2.x, bfr2.y);
        mma_fp16(acc[0][5], ah0[0], ah0[1], ah0[2], ah0[3], bfr2.z, bfr2.w);
        mma_fp16(acc[0][6], ah0[0], ah0[1], ah0[2], ah0[3], bfr3.x, bfr3.y);
        mma_fp16(acc[0][7], ah0[0], ah0[1], ah0[2], ah0[3], bfr3.z, bfr3.w);

#pragma unroll
        for (int u = 0; u < 2; u++) {
            int ci = 2 + u;  // mtile 1
#pragma unroll
            for (int p = 0; p < 2; p++) {
                ull base = fadd2(p ? B1.y : B0.y, pm[ci]);
                ull tt = ffma2(xs[ci], p ? A1.x : A0.x,
                         ffma2(ys[ci], p ? A1.y : A0.y,
                         ffma2(zs[ci], p ? B1.x : B0.x, base)));
                float t0, t1; unpack2(tt, t0, t1);
                float sq0 = fast_sqrt(t0), sq1 = fast_sqrt(t1);
                uint32_t hb;
                asm("cvt.rn.f16x2.f32 %0, %1, %2;" : "=r"(hb) : "f"(sq1), "f"(sq0));
                ah1[u + 2 * p] = hb;
            }
        }
        mma_fp16(acc[1][0], ah1[0], ah1[1], ah1[2], ah1[3], bfr0.x, bfr0.y);
        mma_fp16(acc[1][1], ah1[0], ah1[1], ah1[2], ah1[3], bfr0.z, bfr0.w);
        mma_fp16(acc[1][2], ah1[0], ah1[1], ah1[2], ah1[3], bfr1.x, bfr1.y);
        mma_fp16(acc[1][3], ah1[0], ah1[1], ah1[2], ah1[3], bfr1.z, bfr1.w);
        mma_fp16(acc[1][4], ah1[0], ah1[1], ah1[2], ah1[3], bfr2.x, bfr2.y);
        mma_fp16(acc[1][5], ah1[0], ah1[1], ah1[2], ah1[3], bfr2.z, bfr2.w);
        mma_fp16(acc[1][6], ah1[0], ah1[1], ah1[2], ah1[3], bfr3.x, bfr3.y);
        mma_fp16(acc[1][7], ah1[0], ah1[1], ah1[2], ah1[3], bfr3.z, bfr3.w);
    }

    // epilogue: write partials
    float* part = g_part[ns];
#pragma unroll
    for (int mtile = 0; mtile < 2; mtile++) {
        int rbase = mwb + mtile * 16 + (lane >> 2);
#pragma unroll
        for (int kt = 0; kt < 8; kt++) {
            int c = kt * 8 + (lane & 3) * 2;
            *reinterpret_cast<float2*>(&part[(size_t)rbase * K_DIM + c]) =
                make_float2(acc[mtile][kt][0], acc[mtile][kt][1]);
            *reinterpret_cast<float2*>(&part[(size_t)(rbase + 8) * K_DIM + c]) =
                make_float2(acc[mtile][kt][2], acc[mtile][kt][3]);
        }
    }
}

// ---- reduce: 2 independent float4-quads per thread for MLP ----
__global__ __launch_bounds__(256)
void reduce_parts(float* __restrict__ out) {
    int i = blockIdx.x * 512 + threadIdx.x;
#pragma unroll
    for (int q = 0; q < 2; q++, i += 256) {
        float4 a = __ldg(reinterpret_cast<const float4*>(g_part[0]) + i);
        float4 b = __ldg(reinterpret_cast<const float4*>(g_part[1]) + i);
        float4 c = __ldg(reinterpret_cast<const float4*>(g_part[2]) + i);
        float4 d = __ldg(reinterpret_cast<const float4*>(g_part[3]) + i);
        float4 r;
        r.x = (a.x + b.x) + (c.x + d.x);
        r.y = (a.y + b.y) + (c.y + d.y);
        r.z = (a.z + b.z) + (c.z + d.z);
        r.w = (a.w + b.w) + (c.w + d.w);
        reinterpret_cast<float4*>(out)[i] = r;
    }
}

extern "C" void kernel_launch(void* const* d_in, const int* in_sizes, int n_in,
                              void* d_out, int out_size) {
    const float* Xp  = (const float*)d_in[0];
    const float* X   = (const float*)d_in[1];
    const float* W   = (const float*)d_in[2];
    const float* eps = (const float*)d_in[3];
    float* out = (float*)d_out;

    prep_all<<<BFRAG_U32 / 256, 256>>>(W, X, eps);

    dim3 grid(M_DIM / M_CTA, NSPLIT);   // 128 x 4 = 512 CTAs
    rbf_fp16<<<grid, THREADS>>>(Xp, eps);

    reduce_parts<<<(M_DIM * K_DIM / 4) / 512, 256>>>(out);
}

// round 13
// speedup vs baseline: 1.0308x; 1.0308x over previous
#include <cuda_runtime.h>
#include <cuda_fp16.h>
#include <cstdint>

#define M_DIM 16384
#define N_DIM 8192
#define K_DIM 64

#define THREADS 128            // 4 warps
#define M_CTA 128              // warp covers 32 m
#define NSPLIT 8
#define NRANGE (N_DIM / NSPLIT)      // 1024
#define NSTEPS (NRANGE / 16)         // 64 per CTA

// fp16 B fragments: u32 idx = ((s*4 + ktp)*32 + lane)*4 + j
#define BFRAG_U32 (512 * 4 * 32 * 4)    // 1MB
#define NPAIRS (N_DIM / 2)

typedef unsigned long long ull;

// ---- device scratch ----
__device__ uint32_t g_Bfrag[BFRAG_U32];
// per n-pair: {bx0,bx1, by0,by1, bz0,bz1, c0,c1}; b=-2e^2 x, c=e^2|x|^2+1
__device__ float g_Xpk[NPAIRS * 8];
__device__ float g_part[NSPLIT][M_DIM * K_DIM];  // partials, 32MB (L2-resident)

// ---- helpers ----
__device__ __forceinline__ ull ffma2(ull a, ull b, ull c) {
    ull d; asm("fma.rn.f32x2 %0, %1, %2, %3;" : "=l"(d) : "l"(a), "l"(b), "l"(c)); return d;
}
__device__ __forceinline__ ull fadd2(ull a, ull b) {
    ull d; asm("add.rn.f32x2 %0, %1, %2;" : "=l"(d) : "l"(a), "l"(b)); return d;
}
__device__ __forceinline__ ull splat2(float v) {
    ull d; asm("mov.b64 %0, {%1, %1};" : "=l"(d) : "f"(v)); return d;
}
__device__ __forceinline__ void unpack2(ull p, float& lo, float& hi) {
    asm("mov.b64 {%0, %1}, %2;" : "=f"(lo), "=f"(hi) : "l"(p));
}
__device__ __forceinline__ float fast_sqrt(float x) {
    float r; asm("sqrt.approx.f32 %0, %1;" : "=f"(r) : "f"(x)); return r;
}
__device__ __forceinline__ void mma_fp16(float* d, uint32_t a0, uint32_t a1,
                                         uint32_t a2, uint32_t a3,
                                         uint32_t b0, uint32_t b1) {
    asm volatile(
        "mma.sync.aligned.m16n8k16.row.col.f32.f16.f16.f32 "
        "{%0,%1,%2,%3}, {%4,%5,%6,%7}, {%8,%9}, {%0,%1,%2,%3};"
        : "+f"(d[0]), "+f"(d[1]), "+f"(d[2]), "+f"(d[3])
        : "r"(a0), "r"(a1), "r"(a2), "r"(a3), "r"(b0), "r"(b1));
}

// ---- merged prep: X pair vectors + W fp16 fragment shredding ----
__global__ __launch_bounds__(256)
void prep_all(const float* __restrict__ W, const float* __restrict__ X,
              const float* __restrict__ epsp) {
    int idx = blockIdx.x * 256 + threadIdx.x;

    if (idx < NPAIRS) {   // adjacent pair p -> n = 2p, 2p+1
        float e = *epsp;
        float e2 = e * e;
        const float* x0 = X + (size_t)(2 * idx) * 3;
        float a0 = x0[0], a1 = x0[1], a2 = x0[2];
        float b0 = x0[3], b1 = x0[4], b2 = x0[5];
        float* o = g_Xpk + (size_t)idx * 8;
        o[0] = -2.0f * e2 * a0; o[1] = -2.0f * e2 * b0;
        o[2] = -2.0f * e2 * a1; o[3] = -2.0f * e2 * b1;
        o[4] = -2.0f * e2 * a2; o[5] = -2.0f * e2 * b2;
        o[6] = fmaf(e2, a0 * a0 + a1 * a1 + a2 * a2, 1.0f);
        o[7] = fmaf(e2, b0 * b0 + b1 * b1 + b2 * b2, 1.0f);
    }

    // B fragment shred (idx covers BFRAG_U32)
    {
        int j   = idx & 3;
        int t   = (idx >> 2) & 31;
        int ktp = (idx >> 7) & 3;
        int s   = idx >> 9;

        int kt = ktp * 2 + (j >> 1);
        int km = (t & 3) * 2 + (j & 1) * 8;   // contraction n within step
        int nm = t >> 2;                      // output k within tile
        int kout = kt * 8 + nm;
        int n = s * 16 + km;

        float w0 = W[(size_t)kout * N_DIM + n];
        float w1 = W[(size_t)kout * N_DIM + n + 1];
        uint32_t packed;
        asm("cvt.rn.f16x2.f32 %0, %1, %2;" : "=r"(packed) : "f"(w1), "f"(w0));
        g_Bfrag[idx] = packed;
    }
}

// ---- main kernel (R11 structure, NSPLIT=8) ----
__global__ __launch_bounds__(THREADS, 4)
void rbf_fp16(const float* __restrict__ Xp, const float* __restrict__ epsp) {
    const int tid  = threadIdx.x;
    const int warp = tid >> 5;
    const int lane = tid & 31;
    const int ns   = blockIdx.y;
    const int mwb  = blockIdx.x * M_CTA + warp * 32;   // warp m-base
    const int s0   = ns * NSTEPS;                      // first n-step

    const float e = *epsp;
    const float e2 = e * e;

    // raw Xp coords + Pm = e^2 |xp|^2 for this thread's 4 rows: ci = mtile*2 + u
    ull xs[4], ys[4], zs[4], pm[4];
#pragma unroll
    for (int i = 0; i < 4; i++) {
        int mtile = i >> 1, u = i & 1;
        int m = mwb + mtile * 16 + u * 8 + (lane >> 2);
        float px = Xp[m * 3 + 0], py = Xp[m * 3 + 1], pz = Xp[m * 3 + 2];
        xs[i] = splat2(px);
        ys[i] = splat2(py);
        zs[i] = splat2(pz);
        pm[i] = splat2(e2 * (px * px + py * py + pz * pz));
    }

    float acc[2][8][4];
#pragma unroll
    for (int t = 0; t < 2; t++)
#pragma unroll
        for (int k = 0; k < 8; k++)
#pragma unroll
            for (int j = 0; j < 4; j++) acc[t][k][j] = 0.0f;

    const float* xp = g_Xpk + ((size_t)s0 * 8 + (lane & 3)) * 8;
    const uint4* bf = reinterpret_cast<const uint4*>(g_Bfrag) + (size_t)s0 * 4 * 32 + lane;

    for (int s = 0; s < NSTEPS; s++) {
        // B fragments for this step (4 x LDG.128)
        uint4 bfr0 = __ldg(bf + 0 * 32);
        uint4 bfr1 = __ldg(bf + 1 * 32);
        uint4 bfr2 = __ldg(bf + 2 * 32);
        uint4 bfr3 = __ldg(bf + 3 * 32);
        bf += 4 * 32;

        // pair vectors: p=0 at +0, p=1 at +32 floats; (bx,by) then (bz,c)
        ulonglong2 A0 = *reinterpret_cast<const ulonglong2*>(xp);
        ulonglong2 B0 = *reinterpret_cast<const ulonglong2*>(xp + 4);
        ulonglong2 A1 = *reinterpret_cast<const ulonglong2*>(xp + 32);
        ulonglong2 B1 = *reinterpret_cast<const ulonglong2*>(xp + 36);
        xp += 64;

        // ---- mtile 0: phi -> fragments, then MMAs ----
        uint32_t ah0[4], ah1[4];
#pragma unroll
        for (int u = 0; u < 2; u++) {
            int ci = u;  // mtile 0
#pragma unroll
            for (int p = 0; p < 2; p++) {
                ull base = fadd2(p ? B1.y : B0.y, pm[ci]);
                ull tt = ffma2(xs[ci], p ? A1.x : A0.x,
                         ffma2(ys[ci], p ? A1.y : A0.y,
                         ffma2(zs[ci], p ? B1.x : B0.x, base)));
                float t0, t1; unpack2(tt, t0, t1);
                float sq0 = fast_sqrt(t0), sq1 = fast_sqrt(t1);
                uint32_t hb;
                asm("cvt.rn.f16x2.f32 %0, %1, %2;" : "=r"(hb) : "f"(sq1), "f"(sq0));
                ah0[u + 2 * p] = hb;
            }
        }
        mma_fp16(acc[0][0], ah0[0], ah0[1], ah0[2], ah0[3], bfr0.x, bfr0.y);
        mma_fp16(acc[0][1], ah0[0], ah0[1], ah0[2], ah0[3], bfr0.z, bfr0.w);
        mma_fp16(acc[0][2], ah0[0], ah0[1], ah0[2], ah0[3], bfr1.x, bfr1.y);
        mma_fp16(acc[0][3], ah0[0], ah0[1], ah0[2], ah0[3], bfr1.z, bfr1.w);
        mma_fp16(acc[0][4], ah0[0], ah0[1], ah0[2], ah0[3], bfr2.x, bfr2.y);
        mma_fp16(acc[0][5], ah0[0], ah0[1], ah0[2], ah0[3], bfr2.z, bfr2.w);
        mma_fp16(acc[0][6], ah0[0], ah0[1], ah0[2], ah0[3], bfr3.x, bfr3.y);
        mma_fp16(acc[0][7], ah0[0], ah0[1], ah0[2], ah0[3], bfr3.z, bfr3.w);

        // ---- mtile 1 ----
#pragma unroll
        for (int u = 0; u < 2; u++) {
            int ci = 2 + u;  // mtile 1
#pragma unroll
            for (int p = 0; p < 2; p++) {
                ull base = fadd2(p ? B1.y : B0.y, pm[ci]);
                ull tt = ffma2(xs[ci], p ? A1.x : A0.x,
                         ffma2(ys[ci], p ? A1.y : A0.y,
                         ffma2(zs[ci], p ? B1.x : B0.x, base)));
                float t0, t1; unpack2(tt, t0, t1);
                float sq0 = fast_sqrt(t0), sq1 = fast_sqrt(t1);
                uint32_t hb;
                asm("cvt.rn.f16x2.f32 %0, %1, %2;" : "=r"(hb) : "f"(sq1), "f"(sq0));
                ah1[u + 2 * p] = hb;
            }
        }
        mma_fp16(acc[1][0], ah1[0], ah1[1], ah1[2], ah1[3], bfr0.x, bfr0.y);
        mma_fp16(acc[1][1], ah1[0], ah1[1], ah1[2], ah1[3], bfr0.z, bfr0.w);
        mma_fp16(acc[1][2], ah1[0], ah1[1], ah1[2], ah1[3], bfr1.x, bfr1.y);
        mma_fp16(acc[1][3], ah1[0], ah1[1], ah1[2], ah1[3], bfr1.z, bfr1.w);
        mma_fp16(acc[1][4], ah1[0], ah1[1], ah1[2], ah1[3], bfr2.x, bfr2.y);
        mma_fp16(acc[1][5], ah1[0], ah1[1], ah1[2], ah1[3], bfr2.z, bfr2.w);
        mma_fp16(acc[1][6], ah1[0], ah1[1], ah1[2], ah1[3], bfr3.x, bfr3.y);
        mma_fp16(acc[1][7], ah1[0], ah1[1], ah1[2], ah1[3], bfr3.z, bfr3.w);
    }

    // epilogue: write partials
    float* part = g_part[ns];
#pragma unroll
    for (int mtile = 0; mtile < 2; mtile++) {
        int rbase = mwb + mtile * 16 + (lane >> 2);
#pragma unroll
        for (int kt = 0; kt < 8; kt++) {
            int c = kt * 8 + (lane & 3) * 2;
            *reinterpret_cast<float2*>(&part[(size_t)rbase * K_DIM + c]) =
                make_float2(acc[mtile][kt][0], acc[mtile][kt][1]);
            *reinterpret_cast<float2*>(&part[(size_t)(rbase + 8) * K_DIM + c]) =
                make_float2(acc[mtile][kt][2], acc[mtile][kt][3]);
        }
    }
}

// ---- reduce: 8 partials, one float4 per thread ----
__global__ __launch_bounds__(256)
void reduce_parts(float* __restrict__ out) {
    int i = blockIdx.x * 256 + threadIdx.x;
    float4 r = __ldg(reinterpret_cast<const float4*>(g_part[0]) + i);
#pragma unroll
    for (int p = 1; p < NSPLIT; p++) {
        float4 v = __ldg(reinterpret_cast<const float4*>(g_part[p]) + i);
        r.x += v.x; r.y += v.y; r.z += v.z; r.w += v.w;
    }
    reinterpret_cast<float4*>(out)[i] = r;
}

extern "C" void kernel_launch(void* const* d_in, const int* in_sizes, int n_in,
                              void* d_out, int out_size) {
    const float* Xp  = (const float*)d_in[0];
    const float* X   = (const float*)d_in[1];
    const float* W   = (const float*)d_in[2];
    const float* eps = (const float*)d_in[3];
    float* out = (float*)d_out;

    prep_all<<<BFRAG_U32 / 256, 256>>>(W, X, eps);

    dim3 grid(M_DIM / M_CTA, NSPLIT);   // 128 x 8 = 1024 CTAs
    rbf_fp16<<<grid, THREADS>>>(Xp, eps);

    reduce_parts<<<(M_DIM * K_DIM / 4) / 256, 256>>>(out);
}